// round 14
// baseline (speedup 1.0000x reference)
#include <cuda_runtime.h>
#include <stdint.h>

// MultiEchoNeighborBlock: per-pixel 7x7 KNN (k=9) over point distances,
// gather range values in exact rank order, 20->32 linear + leaky relu.
//
// R14 vs R13 (139.6us, alu=66.7, fma=36.8, issue=76.6):
//  1. Distances packed ACROSS echoes (lane0=echo0, lane1=echo1): 3 add2 +
//     3 mul2 + 2 add2 compute both echoes' (dx^2+dy^2)+dz^2 in reference
//     order; packed f32x2 ops are two independent IEEE f32 ops, so each
//     lane is bit-identical to the scalar reference chain. IEEE sqrt kept.
//  2. Echo1 insert = insM: keys via FMNMX carry identity (exact), values
//     via asm setp.lt.f32 + 2x selp.f32 -> if ptxas emits FSEL (fma pipe),
//     stage = 3 alu + 2 fma (balanced 5 ops); if SEL (alu), degenerates to
//     insA cost (no regression). Echo0 keeps insF (3 alu + 3 fma, known).
// Stable-order semantics unchanged (R5 proof): all compares use the ORIGINAL
// incoming key; ties sink the later-index incoming; residents never
// re-compared. Payload moves bit-exact (selp) or <=1ulp (insF blends).

#define HH 64
#define WW 2048
#define HWP (HH * WW)
#define NCH 8
#define BX 128
#define BY 2
#define TPB (BX * BY)
#define TW (BX + 6)
#define TH (BY + 6)

#define PACK2(out, lo, hi) \
    asm("mov.b64 %0, {%1, %2};" : "=l"(out) : "r"(__float_as_uint(lo)), "r"(__float_as_uint(hi)))
#define PACK2S(out, v) \
    asm("mov.b64 %0, {%1, %1};" : "=l"(out) : "r"(__float_as_uint(v)))
#define UNPACK2(lo, hi, in) \
    do { unsigned _ulo, _uhi; \
         asm("mov.b64 {%0, %1}, %2;" : "=r"(_ulo), "=r"(_uhi) : "l"(in)); \
         lo = __uint_as_float(_ulo); hi = __uint_as_float(_uhi); } while (0)
#define ADD2(out, a, b) asm("add.rn.f32x2 %0, %1, %2;" : "=l"(out) : "l"(a), "l"(b))
#define MUL2(out, a, b) asm("mul.rn.f32x2 %0, %1, %2;" : "=l"(out) : "l"(a), "l"(b))
#define FMA2(out, a, b, c) \
    asm("fma.rn.f32x2 %0, %1, %2, %3;" : "=l"(out) : "l"(a), "l"(b), "l"(c))

// fma-flavor stable insert (M stages): FSET + 2 FMNMX (alu) + FADD + 2 FFMA
// (fma). Mask uses ORIGINAL kin; FFMA blends are value-moves (<=1ulp,
// payloads only feed the linear layer).
template <int M>
__device__ __forceinline__ void insF(float kin, float vin,
                                     float (&ak)[9], float (&av)[9]) {
    float ck = kin, cv = vin;
#pragma unroll
    for (int j = 0; j < M; ++j) {
        float aj = ak[j];
        float m;
        asm("set.lt.f32.f32 %0, %1, %2;" : "=f"(m) : "f"(kin), "f"(aj));
        float mn = fminf(ck, aj);
        float mx = fmaxf(ck, aj);
        float diff = __fadd_rn(cv, -av[j]);
        av[j] = __fmaf_rn(m, diff, av[j]);
        cv    = __fmaf_rn(-m, diff, cv);
        ak[j] = mn;
        ck = mx;
    }
}

// insM stable insert (M stages): keys via FMNMX carry identity (exact:
// before insertion point carry=kin>=ak[j] -> min keeps resident; after,
// carry=shifted resident <= ak[j] -> min=carry, max=next carry; ties pick
// equal value either way). Values via setp.lt.f32 on ORIGINAL kin + selp.f32
// pair (bit-exact moves; FSEL if ptxas cooperates, SEL otherwise).
template <int M>
__device__ __forceinline__ void insM(float kin, float vin,
                                     float (&ak)[9], float (&av)[9]) {
    float ck = kin, cv = vin;
#pragma unroll
    for (int j = 0; j < M; ++j) {
        float aj = ak[j];
        float mn = fminf(ck, aj);
        float mx = fmaxf(ck, aj);
        float nav, ncv;
        asm("{\n\t"
            ".reg .pred p;\n\t"
            "setp.lt.f32 p, %2, %3;\n\t"
            "selp.f32 %0, %4, %5, p;\n\t"
            "selp.f32 %1, %5, %4, p;\n\t"
            "}"
            : "=f"(nav), "=f"(ncv)
            : "f"(kin), "f"(aj), "f"(cv), "f"(av[j]));
        av[j] = nav;
        cv = ncv;
        ak[j] = mn;
        ck = mx;
    }
}

struct QP {
    uint64_t nqx2, nqy2, nqz2;   // packed (-q0, -q1) per coordinate
};

// One candidate into both echoes: packed-across-echo distance, then inserts.
template <int M>
__device__ __forceinline__ void do_cand(const float4 p, const QP& q,
                                        float (&k0)[9], float (&v0)[9],
                                        float (&k1)[9], float (&v1)[9]) {
    uint64_t px2, py2, pz2;
    PACK2S(px2, p.x);
    PACK2S(py2, p.y);
    PACK2S(pz2, p.z);
    uint64_t dx2, dy2, dz2, sx2, sy2, sz2, t2, s2;
    ADD2(dx2, px2, q.nqx2);   // (p - q) per lane; squares == (q - p)^2
    ADD2(dy2, py2, q.nqy2);
    ADD2(dz2, pz2, q.nqz2);
    MUL2(sx2, dx2, dx2);
    MUL2(sy2, dy2, dy2);
    MUL2(sz2, dz2, dz2);
    ADD2(t2, sx2, sy2);       // (dx^2 + dy^2) ...
    ADD2(s2, t2, sz2);        // ... + dz^2   (reference order per lane)
    float s0, s1;
    UNPACK2(s0, s1, s2);
    insF<M>(__fsqrt_rn(s0), p.w, k0, v0);
    insM<M>(__fsqrt_rn(s1), p.w, k1, v1);
}

__global__ __launch_bounds__(TPB, 4)
void knn_block_kernel(const float* __restrict__ x,
                      const float* __restrict__ rw,
                      float* __restrict__ out) {
    __shared__ float4 tile[TH][TW];
    __shared__ float wt[20][32];

    const int tid = threadIdx.x;
    const int b = blockIdx.z;
    const int h0 = blockIdx.y * BY;
    const int w0 = blockIdx.x * BX;
    const float* X = x + (size_t)b * NCH * HWP;

    for (int i = tid; i < 640; i += TPB) {
        wt[i % 20][i / 20] = rw[i];
    }
    for (int i = tid; i < TH * TW; i += TPB) {
        int r = i / TW, c = i % TW;
        int gh = h0 - 3 + r, gw = w0 - 3 + c;
        float4 v = make_float4(0.f, 0.f, 0.f, 0.f);
        if (gh >= 0 && gh < HH && gw >= 0 && gw < WW) {
            int o = gh * WW + gw;
            v.x = X[2 * HWP + o];
            v.y = X[3 * HWP + o];
            v.z = X[4 * HWP + o];
            v.w = X[0 * HWP + o];
        }
        tile[r][c] = v;
    }
    __syncthreads();

    const int tx = tid % BX;
    const int ty = tid / BX;
    const int h = h0 + ty;
    const int w = w0 + tx;
    const int pix = h * WW + w;

    const float4 c4 = tile[ty + 3][tx + 3];
    float q1x = X[5 * HWP + pix];
    float q1y = X[6 * HWP + pix];
    float q1z = X[7 * HWP + pix];
    QP q;
    PACK2(q.nqx2, -c4.x, -q1x);
    PACK2(q.nqy2, -c4.y, -q1y);
    PACK2(q.nqz2, -c4.z, -q1z);
    const float r1c = X[1 * HWP + pix];

    const float INF = __int_as_float(0x7f800000);
    float ak0[9], av0[9], ak1[9], av1[9];
#pragma unroll
    for (int j = 0; j < 9; ++j) {
        ak0[j] = INF; av0[j] = 0.f;
        ak1[j] = INF; av1[j] = 0.f;
    }

    // Triangle phase: candidate i needs only min(i+1,9) chain stages.
    {
        const float4* r0 = &tile[ty + 0][tx];
        do_cand<1>(r0[0], q, ak0, av0, ak1, av1);
        do_cand<2>(r0[1], q, ak0, av0, ak1, av1);
        do_cand<3>(r0[2], q, ak0, av0, ak1, av1);
        do_cand<4>(r0[3], q, ak0, av0, ak1, av1);
        do_cand<5>(r0[4], q, ak0, av0, ak1, av1);
        do_cand<6>(r0[5], q, ak0, av0, ak1, av1);
        do_cand<7>(r0[6], q, ak0, av0, ak1, av1);
        const float4* r1 = &tile[ty + 1][tx];
        do_cand<8>(r1[0], q, ak0, av0, ak1, av1);
        do_cand<9>(r1[1], q, ak0, av0, ak1, av1);
        do_cand<9>(r1[2], q, ak0, av0, ak1, av1);
        do_cand<9>(r1[3], q, ak0, av0, ak1, av1);
        do_cand<9>(r1[4], q, ak0, av0, ak1, av1);
        do_cand<9>(r1[5], q, ak0, av0, ak1, av1);
        do_cand<9>(r1[6], q, ak0, av0, ak1, av1);
    }
    // Steady phase: rows 2..6.
#pragma unroll 1
    for (int dy = 2; dy < 7; ++dy) {
        const float4* row = &tile[ty + dy][tx];
#pragma unroll
        for (int dx = 0; dx < 7; ++dx)
            do_cand<9>(row[dx], q, ak0, av0, ak1, av1);
    }

    float feats[20];
#pragma unroll
    for (int s = 0; s < 9; ++s) {
        feats[s]      = av0[s];
        feats[10 + s] = av1[s];
    }
    feats[9]  = c4.w;
    feats[19] = r1c;

    // 20 -> 32 linear via packed f32x2 FFMA (two independent IEEE f32 FMAs).
    uint64_t acc2[16];
#pragma unroll
    for (int k = 0; k < 16; ++k) acc2[k] = 0ull;
#pragma unroll
    for (int c = 0; c < 20; ++c) {
        uint64_t f2;
        PACK2S(f2, feats[c]);
        const ulonglong2* wp = (const ulonglong2*)&wt[c][0];
#pragma unroll
        for (int k4 = 0; k4 < 8; ++k4) {
            ulonglong2 wv = wp[k4];
            FMA2(acc2[k4 * 2 + 0], f2, wv.x, acc2[k4 * 2 + 0]);
            FMA2(acc2[k4 * 2 + 1], f2, wv.y, acc2[k4 * 2 + 1]);
        }
    }

    float* O = out + (size_t)b * 32 * HWP + pix;
#pragma unroll
    for (int k2 = 0; k2 < 16; ++k2) {
        float v0, v1;
        UNPACK2(v0, v1, acc2[k2]);
        v0 = fmaxf(v0, 0.01f * v0);   // leaky_relu(0.01)
        v1 = fmaxf(v1, 0.01f * v1);
        O[(size_t)(2 * k2 + 0) * HWP] = v0;
        O[(size_t)(2 * k2 + 1) * HWP] = v1;
    }
}

extern "C" void kernel_launch(void* const* d_in, const int* in_sizes, int n_in,
                              void* d_out, int out_size) {
    const float* x  = (const float*)d_in[0];
    const float* rw = (const float*)d_in[1];
    if (n_in >= 2 && in_sizes[0] == 640) {
        const float* t = x; x = rw; rw = t;
    }
    dim3 grid(WW / BX, HH / BY, 4);
    knn_block_kernel<<<grid, TPB>>>(x, rw, (float*)d_out);
}

// round 15
// speedup vs baseline: 1.0327x; 1.0327x over previous
#include <cuda_runtime.h>
#include <stdint.h>

// MultiEchoNeighborBlock: per-pixel 7x7 KNN (k=9) over point distances,
// gather range values in exact rank order, 20->32 linear + leaky relu.
//
// R15 = R14's across-echo packed distances + R13's insert flavor mix.
// R14 post-mortem: insM's asm lacked early-clobber on outputs -> selp #1
// could clobber selp #2's inputs -> payload corruption (rel_err 1.7e-4).
// Profile also proved selp lowers to alu SEL (no FSEL), so insM had no cost
// advantage over insA. insM removed.
//  - Distances packed ACROSS echoes (lane0=echo0, lane1=echo1): 3 add2 +
//    3 mul2 + 2 add2 for both echoes' (dx^2+dy^2)+dz^2; each lane is an
//    independent IEEE f32 chain in reference order; (p-q)^2 == (q-p)^2
//    bitwise; IEEE sqrt kept -> tie pattern bit-identical to reference.
//  - Echo0 insert = insF (3 alu + 3 fma); echo1 alternates insA (5 alu) /
//    insF by dx parity -> calibrated pipe balance (R13: alu 66.7, fma 36.8).
// Stable-insert semantics (R5 proof): compares use the ORIGINAL incoming
// key; ties sink the later-index incoming; residents never re-compared.

#define HH 64
#define WW 2048
#define HWP (HH * WW)
#define NCH 8
#define BX 128
#define BY 2
#define TPB (BX * BY)
#define TW (BX + 6)
#define TH (BY + 6)

#define PACK2(out, lo, hi) \
    asm("mov.b64 %0, {%1, %2};" : "=l"(out) : "r"(__float_as_uint(lo)), "r"(__float_as_uint(hi)))
#define PACK2S(out, v) \
    asm("mov.b64 %0, {%1, %1};" : "=l"(out) : "r"(__float_as_uint(v)))
#define UNPACK2(lo, hi, in) \
    do { unsigned _ulo, _uhi; \
         asm("mov.b64 {%0, %1}, %2;" : "=r"(_ulo), "=r"(_uhi) : "l"(in)); \
         lo = __uint_as_float(_ulo); hi = __uint_as_float(_uhi); } while (0)
#define ADD2(out, a, b) asm("add.rn.f32x2 %0, %1, %2;" : "=l"(out) : "l"(a), "l"(b))
#define MUL2(out, a, b) asm("mul.rn.f32x2 %0, %1, %2;" : "=l"(out) : "l"(a), "l"(b))
#define FMA2(out, a, b, c) \
    asm("fma.rn.f32x2 %0, %1, %2, %3;" : "=l"(out) : "l"(a), "l"(b), "l"(c))

// alu-flavor stable insert (M stages): 1 FSETP + 4 SEL. Independent per-slot
// predicates (array sorted => kin<ak[j] monotone in j == sticky form).
template <int M>
__device__ __forceinline__ void insA(float kin, float vin,
                                     float (&ak)[9], float (&av)[9]) {
    float ck = kin, cv = vin;
#pragma unroll
    for (int j = 0; j < M; ++j) {
        bool pj = kin < ak[j];
        float tk = ak[j], tv = av[j];
        ak[j] = pj ? ck : tk;
        av[j] = pj ? cv : tv;
        ck = pj ? tk : ck;
        cv = pj ? tv : cv;
    }
}

// fma-flavor stable insert (M stages): FSET + 2 FMNMX (alu) + FADD + 2 FFMA
// (fma). Mask uses ORIGINAL kin; FFMA blends are value-moves (<=1ulp,
// payloads only feed the linear layer, never an ordering decision).
template <int M>
__device__ __forceinline__ void insF(float kin, float vin,
                                     float (&ak)[9], float (&av)[9]) {
    float ck = kin, cv = vin;
#pragma unroll
    for (int j = 0; j < M; ++j) {
        float aj = ak[j];
        float m;
        asm("set.lt.f32.f32 %0, %1, %2;" : "=f"(m) : "f"(kin), "f"(aj));
        float mn = fminf(ck, aj);
        float mx = fmaxf(ck, aj);
        float diff = __fadd_rn(cv, -av[j]);
        av[j] = __fmaf_rn(m, diff, av[j]);
        cv    = __fmaf_rn(-m, diff, cv);
        ak[j] = mn;
        ck = mx;
    }
}

struct QP {
    uint64_t nqx2, nqy2, nqz2;   // packed (-q0, -q1) per coordinate
};

// One candidate into both echoes. AFLAV=1 -> echo1 uses insA, else insF.
template <int M, int AFLAV>
__device__ __forceinline__ void do_cand(const float4 p, const QP& q,
                                        float (&k0)[9], float (&v0)[9],
                                        float (&k1)[9], float (&v1)[9]) {
    uint64_t px2, py2, pz2;
    PACK2S(px2, p.x);
    PACK2S(py2, p.y);
    PACK2S(pz2, p.z);
    uint64_t dx2, dy2, dz2, sx2, sy2, sz2, t2, s2;
    ADD2(dx2, px2, q.nqx2);   // (p - q) per lane; squares == (q - p)^2
    ADD2(dy2, py2, q.nqy2);
    ADD2(dz2, pz2, q.nqz2);
    MUL2(sx2, dx2, dx2);
    MUL2(sy2, dy2, dy2);
    MUL2(sz2, dz2, dz2);
    ADD2(t2, sx2, sy2);       // (dx^2 + dy^2) ...
    ADD2(s2, t2, sz2);        // ... + dz^2   (reference order per lane)
    float s0, s1;
    UNPACK2(s0, s1, s2);
    insF<M>(__fsqrt_rn(s0), p.w, k0, v0);
    float dist1 = __fsqrt_rn(s1);
    if (AFLAV) insA<M>(dist1, p.w, k1, v1);
    else       insF<M>(dist1, p.w, k1, v1);
}

__global__ __launch_bounds__(TPB, 4)
void knn_block_kernel(const float* __restrict__ x,
                      const float* __restrict__ rw,
                      float* __restrict__ out) {
    __shared__ float4 tile[TH][TW];
    __shared__ float wt[20][32];

    const int tid = threadIdx.x;
    const int b = blockIdx.z;
    const int h0 = blockIdx.y * BY;
    const int w0 = blockIdx.x * BX;
    const float* X = x + (size_t)b * NCH * HWP;

    for (int i = tid; i < 640; i += TPB) {
        wt[i % 20][i / 20] = rw[i];
    }
    for (int i = tid; i < TH * TW; i += TPB) {
        int r = i / TW, c = i % TW;
        int gh = h0 - 3 + r, gw = w0 - 3 + c;
        float4 v = make_float4(0.f, 0.f, 0.f, 0.f);
        if (gh >= 0 && gh < HH && gw >= 0 && gw < WW) {
            int o = gh * WW + gw;
            v.x = X[2 * HWP + o];
            v.y = X[3 * HWP + o];
            v.z = X[4 * HWP + o];
            v.w = X[0 * HWP + o];
        }
        tile[r][c] = v;
    }
    __syncthreads();

    const int tx = tid % BX;
    const int ty = tid / BX;
    const int h = h0 + ty;
    const int w = w0 + tx;
    const int pix = h * WW + w;

    const float4 c4 = tile[ty + 3][tx + 3];
    float q1x = X[5 * HWP + pix];
    float q1y = X[6 * HWP + pix];
    float q1z = X[7 * HWP + pix];
    QP q;
    PACK2(q.nqx2, -c4.x, -q1x);
    PACK2(q.nqy2, -c4.y, -q1y);
    PACK2(q.nqz2, -c4.z, -q1z);
    const float r1c = X[1 * HWP + pix];

    const float INF = __int_as_float(0x7f800000);
    float ak0[9], av0[9], ak1[9], av1[9];
#pragma unroll
    for (int j = 0; j < 9; ++j) {
        ak0[j] = INF; av0[j] = 0.f;
        ak1[j] = INF; av1[j] = 0.f;
    }

    // Triangle phase: candidate i needs only min(i+1,9) chain stages.
    {
        const float4* r0 = &tile[ty + 0][tx];
        do_cand<1, 1>(r0[0], q, ak0, av0, ak1, av1);
        do_cand<2, 0>(r0[1], q, ak0, av0, ak1, av1);
        do_cand<3, 1>(r0[2], q, ak0, av0, ak1, av1);
        do_cand<4, 0>(r0[3], q, ak0, av0, ak1, av1);
        do_cand<5, 1>(r0[4], q, ak0, av0, ak1, av1);
        do_cand<6, 0>(r0[5], q, ak0, av0, ak1, av1);
        do_cand<7, 1>(r0[6], q, ak0, av0, ak1, av1);
        const float4* r1 = &tile[ty + 1][tx];
        do_cand<8, 0>(r1[0], q, ak0, av0, ak1, av1);
        do_cand<9, 1>(r1[1], q, ak0, av0, ak1, av1);
        do_cand<9, 0>(r1[2], q, ak0, av0, ak1, av1);
        do_cand<9, 1>(r1[3], q, ak0, av0, ak1, av1);
        do_cand<9, 0>(r1[4], q, ak0, av0, ak1, av1);
        do_cand<9, 1>(r1[5], q, ak0, av0, ak1, av1);
        do_cand<9, 0>(r1[6], q, ak0, av0, ak1, av1);
    }
    // Steady phase: rows 2..6; echo1 flavor alternates by dx parity.
#pragma unroll 1
    for (int dy = 2; dy < 7; ++dy) {
        const float4* row = &tile[ty + dy][tx];
        do_cand<9, 1>(row[0], q, ak0, av0, ak1, av1);
        do_cand<9, 0>(row[1], q, ak0, av0, ak1, av1);
        do_cand<9, 1>(row[2], q, ak0, av0, ak1, av1);
        do_cand<9, 0>(row[3], q, ak0, av0, ak1, av1);
        do_cand<9, 1>(row[4], q, ak0, av0, ak1, av1);
        do_cand<9, 0>(row[5], q, ak0, av0, ak1, av1);
        do_cand<9, 1>(row[6], q, ak0, av0, ak1, av1);
    }

    float feats[20];
#pragma unroll
    for (int s = 0; s < 9; ++s) {
        feats[s]      = av0[s];
        feats[10 + s] = av1[s];
    }
    feats[9]  = c4.w;
    feats[19] = r1c;

    // 20 -> 32 linear via packed f32x2 FFMA (two independent IEEE f32 FMAs).
    uint64_t acc2[16];
#pragma unroll
    for (int k = 0; k < 16; ++k) acc2[k] = 0ull;
#pragma unroll
    for (int c = 0; c < 20; ++c) {
        uint64_t f2;
        PACK2S(f2, feats[c]);
        const ulonglong2* wp = (const ulonglong2*)&wt[c][0];
#pragma unroll
        for (int k4 = 0; k4 < 8; ++k4) {
            ulonglong2 wv = wp[k4];
            FMA2(acc2[k4 * 2 + 0], f2, wv.x, acc2[k4 * 2 + 0]);
            FMA2(acc2[k4 * 2 + 1], f2, wv.y, acc2[k4 * 2 + 1]);
        }
    }

    float* O = out + (size_t)b * 32 * HWP + pix;
#pragma unroll
    for (int k2 = 0; k2 < 16; ++k2) {
        float v0, v1;
        UNPACK2(v0, v1, acc2[k2]);
        v0 = fmaxf(v0, 0.01f * v0);   // leaky_relu(0.01)
        v1 = fmaxf(v1, 0.01f * v1);
        O[(size_t)(2 * k2 + 0) * HWP] = v0;
        O[(size_t)(2 * k2 + 1) * HWP] = v1;
    }
}

extern "C" void kernel_launch(void* const* d_in, const int* in_sizes, int n_in,
                              void* d_out, int out_size) {
    const float* x  = (const float*)d_in[0];
    const float* rw = (const float*)d_in[1];
    if (n_in >= 2 && in_sizes[0] == 640) {
        const float* t = x; x = rw; rw = t;
    }
    dim3 grid(WW / BX, HH / BY, 4);
    knn_block_kernel<<<grid, TPB>>>(x, rw, (float*)d_out);
}